// round 1
// baseline (speedup 1.0000x reference)
#include <cuda_runtime.h>
#include <math.h>

#define NB   16
#define CIN  256
#define HH   96
#define WW   96
#define MIP  64
#define SEQ  192

// ---- scratch (device globals; no allocation allowed) ----
__device__ float g_y0[NB * CIN * SEQ];   // pooled + concat (b, 256, 192)
__device__ float g_y1[NB * MIP * SEQ];   // after conv1x1 #1 (b, 64, 192)
__device__ float g_y2[NB * MIP * SEQ];   // after involution1 + BN + hswish
__device__ float g_ah[NB * CIN * HH];    // sigmoid attention (h)
__device__ float g_aw[NB * CIN * WW];    // sigmoid attention (w)

// ===================== K1: row & col means per (b,c) plane =====================
// grid = NB*CIN blocks, block = 192 threads
__global__ void k_means(const float* __restrict__ x) {
    __shared__ float sp[96 * 97];  // padded to avoid bank conflicts on row sums
    const int bc  = blockIdx.x;
    const int tid = threadIdx.x;
    const float4* xp = (const float4*)(x + (size_t)bc * (96 * 96));

    // load plane (2304 float4), scatter to padded smem
    for (int i = tid; i < 96 * 24; i += 192) {
        float4 v = xp[i];
        int r  = i / 24;
        int c4 = (i % 24) * 4;
        float* d = &sp[r * 97 + c4];
        d[0] = v.x; d[1] = v.y; d[2] = v.z; d[3] = v.w;
    }
    __syncthreads();

    float s = 0.f;
    if (tid < 96) {                       // row mean (x_h), p = tid
        const float* rp = &sp[tid * 97];
        #pragma unroll 8
        for (int j = 0; j < 96; j++) s += rp[j];
    } else {                              // col mean (x_w), p = 96 + (tid-96)
        int c = tid - 96;
        #pragma unroll 8
        for (int i = 0; i < 96; i++) s += sp[i * 97 + c];
    }
    g_y0[(size_t)bc * SEQ + tid] = s * (1.f / 96.f);
}

// ===================== K2: conv1x1 256 -> 64 over the 192-seq =====================
// grid = NB*6 blocks (chunks of 32 positions), block = 256
__global__ void k_conv1(const float* __restrict__ w, const float* __restrict__ bias) {
    const int b  = blockIdx.x / 6;
    const int ch = blockIdx.x % 6;
    const int o  = threadIdx.x >> 2;       // 0..63
    const int q  = threadIdx.x & 3;        // 0..3
    const int p  = ch * 32 + q * 8;        // 8 consecutive positions

    const float* y0b = g_y0 + (size_t)b * CIN * SEQ + p;
    const float* wr  = w + o * CIN;

    float acc[8];
    #pragma unroll
    for (int j = 0; j < 8; j++) acc[j] = 0.f;

    for (int c = 0; c < CIN; c++) {
        float wv = __ldg(wr + c);
        const float4* yp = (const float4*)(y0b + (size_t)c * SEQ);
        float4 v0 = __ldg(yp);
        float4 v1 = __ldg(yp + 1);
        acc[0] += wv * v0.x; acc[1] += wv * v0.y; acc[2] += wv * v0.z; acc[3] += wv * v0.w;
        acc[4] += wv * v1.x; acc[5] += wv * v1.y; acc[6] += wv * v1.z; acc[7] += wv * v1.w;
    }
    float bo = bias[o];
    float* outp = g_y1 + ((size_t)b * MIP + o) * SEQ + p;
    #pragma unroll
    for (int j = 0; j < 8; j++) outp[j] = acc[j] + bo;
}

// ===================== K3: involution (192-seq) + BN + hswish =====================
// grid = NB*4 (chunks of 48), block = 256
__global__ void k_inv1(const float* __restrict__ w1, const float* __restrict__ b1,
                       const float* __restrict__ w2, const float* __restrict__ b2,
                       const float* __restrict__ bng, const float* __restrict__ bnb,
                       const float* __restrict__ bnm, const float* __restrict__ bnv) {
    __shared__ float sy[64 * 54];   // y1 chunk + halo 3 (zero outside [0,192))
    __shared__ float st[16 * 48];
    __shared__ float sg[28 * 48];

    const int b   = blockIdx.x >> 2;
    const int p0  = (blockIdx.x & 3) * 48;
    const int tid = threadIdx.x;

    for (int i = tid; i < 64 * 54; i += 256) {
        int c = i / 54, p = i % 54;
        int gp = p0 + p - 3;
        sy[i] = (gp >= 0 && gp < SEQ) ? g_y1[((size_t)b * MIP + c) * SEQ + gp] : 0.f;
    }
    __syncthreads();

    // t = w1 @ y1 + b1   (16 x 48)
    for (int i = tid; i < 16 * 48; i += 256) {
        int r = i / 48, p = i % 48;
        float acc = __ldg(b1 + r);
        const float* wr = w1 + r * 64;
        #pragma unroll 8
        for (int c = 0; c < 64; c++) acc += __ldg(wr + c) * sy[c * 54 + 3 + p];
        st[i] = acc;
    }
    __syncthreads();

    // wgt: only rows k = kh*7+3 per group (28 x 48)
    for (int i = tid; i < 28 * 48; i += 256) {
        int r = i / 48, p = i % 48;
        int g = r / 7, kh = r % 7;
        int row = g * 49 + kh * 7 + 3;
        float acc = __ldg(b2 + row);
        const float* wr = w2 + row * 16;
        #pragma unroll
        for (int c = 0; c < 16; c++) acc += __ldg(wr + c) * st[c * 48 + p];
        sg[i] = acc;
    }
    __syncthreads();

    // involution + BN + hswish
    for (int i = tid; i < 64 * 48; i += 256) {
        int c = i / 48, p = i % 48;
        int g = c >> 4;
        float acc = 0.f;
        #pragma unroll
        for (int kh = 0; kh < 7; kh++)
            acc += sg[(g * 7 + kh) * 48 + p] * sy[c * 54 + p + kh];
        float sc = __ldg(bng + c) * rsqrtf(__ldg(bnv + c) + 1e-5f);
        float v  = (acc - __ldg(bnm + c)) * sc + __ldg(bnb + c);
        float hs = v * fminf(fmaxf(v + 3.f, 0.f), 6.f) * (1.f / 6.f);
        g_y2[((size_t)b * MIP + c) * SEQ + p0 + p] = hs;
    }
}

// ========== K4: involution (96-seq, h or w half) + conv1x1 64->256 + sigmoid ==========
// grid = NB*2*4 = 128 (b, half, chunk of 24), block = 256
__global__ void k_inv2(const float* __restrict__ w1h, const float* __restrict__ b1h,
                       const float* __restrict__ w2h, const float* __restrict__ b2h,
                       const float* __restrict__ wch, const float* __restrict__ bch,
                       const float* __restrict__ w1w, const float* __restrict__ b1w,
                       const float* __restrict__ w2w, const float* __restrict__ b2w,
                       const float* __restrict__ wcw, const float* __restrict__ bcw) {
    __shared__ float sy[64 * 30];     // y half-chunk + halo
    __shared__ float st[16 * 24];
    __shared__ float sg[28 * 24];
    __shared__ float sz[64 * 24];     // involution output
    __shared__ float swt[256 * 9];    // conv weight c-tile (pad 9)

    const int bid  = blockIdx.x;
    const int b    = bid >> 3;
    const int rest = bid & 7;
    const int half = rest >> 2;       // 0 = h, 1 = w
    const int p0   = (rest & 3) * 24;
    const int tid  = threadIdx.x;

    const float* w1 = half ? w1w : w1h;
    const float* b1 = half ? b1w : b1h;
    const float* w2 = half ? w2w : w2h;
    const float* b2 = half ? b2w : b2h;
    const float* wc = half ? wcw : wch;
    const float* bc = half ? bcw : bch;
    float* outbuf   = half ? g_aw : g_ah;

    for (int i = tid; i < 64 * 30; i += 256) {
        int c = i / 30, p = i % 30;
        int gp = p0 + p - 3;
        sy[i] = (gp >= 0 && gp < 96)
              ? g_y2[((size_t)b * MIP + c) * SEQ + half * 96 + gp] : 0.f;
    }
    __syncthreads();

    for (int i = tid; i < 16 * 24; i += 256) {
        int r = i / 24, p = i % 24;
        float acc = __ldg(b1 + r);
        const float* wr = w1 + r * 64;
        #pragma unroll 8
        for (int c = 0; c < 64; c++) acc += __ldg(wr + c) * sy[c * 30 + 3 + p];
        st[i] = acc;
    }
    __syncthreads();

    for (int i = tid; i < 28 * 24; i += 256) {
        int r = i / 24, p = i % 24;
        int g = r / 7, kh = r % 7;
        int row = half ? (g * 49 + 21 + kh) : (g * 49 + kh * 7 + 3);
        float acc = __ldg(b2 + row);
        const float* wr = w2 + row * 16;
        #pragma unroll
        for (int c = 0; c < 16; c++) acc += __ldg(wr + c) * st[c * 24 + p];
        sg[i] = acc;
    }
    __syncthreads();

    for (int i = tid; i < 64 * 24; i += 256) {
        int c = i / 24, p = i % 24;
        int g = c >> 4;
        float acc = 0.f;
        #pragma unroll
        for (int kh = 0; kh < 7; kh++)
            acc += sg[(g * 7 + kh) * 24 + p] * sy[c * 30 + p + kh];
        sz[i] = acc;
    }
    __syncthreads();

    // conv 64 -> 256 + sigmoid; thread tile: 4 outputs x 6 positions
    const int og = tid >> 2;   // 0..63  -> o = og*4+k
    const int q  = tid & 3;    // 0..3   -> p = q*6+j

    float acc[4][6];
    #pragma unroll
    for (int k = 0; k < 4; k++)
        #pragma unroll
        for (int j = 0; j < 6; j++) acc[k][j] = 0.f;

    for (int c0 = 0; c0 < 64; c0 += 8) {
        for (int i = tid; i < 2048; i += 256) {
            int o = i >> 3, cc = i & 7;
            swt[o * 9 + cc] = __ldg(wc + o * 64 + c0 + cc);
        }
        __syncthreads();
        #pragma unroll
        for (int cc = 0; cc < 8; cc++) {
            float zv[6];
            #pragma unroll
            for (int j = 0; j < 6; j++) zv[j] = sz[(c0 + cc) * 24 + q * 6 + j];
            #pragma unroll
            for (int k = 0; k < 4; k++) {
                float wv = swt[(og * 4 + k) * 9 + cc];
                #pragma unroll
                for (int j = 0; j < 6; j++) acc[k][j] += wv * zv[j];
            }
        }
        __syncthreads();
    }

    #pragma unroll
    for (int k = 0; k < 4; k++) {
        int o = og * 4 + k;
        float bo = __ldg(bc + o);
        #pragma unroll
        for (int j = 0; j < 6; j++) {
            float v = acc[k][j] + bo;
            float s = 1.f / (1.f + __expf(-v));
            outbuf[((size_t)b * CIN + o) * 96 + p0 + q * 6 + j] = s;
        }
    }
}

// ===================== K5: out = x * a_h * a_w (float4) =====================
// grid = (9, NB*CIN), block = 256; plane = 96*24 float4
__global__ void k_final(const float4* __restrict__ x, float4* __restrict__ out) {
    int t = blockIdx.x * 256 + threadIdx.x;
    if (t >= 96 * 24) return;
    int bc = blockIdx.y;
    int i  = t / 24;
    int jf = t % 24;
    float h = __ldg(g_ah + (size_t)bc * 96 + i);
    const float4* aw4 = (const float4*)g_aw;
    float4 wv = __ldg(aw4 + (size_t)bc * 24 + jf);
    size_t idx = (size_t)bc * (96 * 24) + t;
    float4 xv = __ldg(x + idx);
    float4 r;
    r.x = xv.x * h * wv.x;
    r.y = xv.y * h * wv.y;
    r.z = xv.z * h * wv.z;
    r.w = xv.w * h * wv.w;
    out[idx] = r;
}

// ===================== launch =====================
extern "C" void kernel_launch(void* const* d_in, const int* in_sizes, int n_in,
                              void* d_out, int out_size) {
    const float* x     = (const float*)d_in[0];
    const float* w_c1  = (const float*)d_in[1];
    const float* b_c1  = (const float*)d_in[2];
    const float* i1w1  = (const float*)d_in[3];
    const float* i1b1  = (const float*)d_in[4];
    const float* i1w2  = (const float*)d_in[5];
    const float* i1b2  = (const float*)d_in[6];
    const float* bng   = (const float*)d_in[7];
    const float* bnb   = (const float*)d_in[8];
    const float* bnm   = (const float*)d_in[9];
    const float* bnv   = (const float*)d_in[10];
    const float* ihw1  = (const float*)d_in[11];
    const float* ihb1  = (const float*)d_in[12];
    const float* ihw2  = (const float*)d_in[13];
    const float* ihb2  = (const float*)d_in[14];
    const float* w_h   = (const float*)d_in[15];
    const float* b_h   = (const float*)d_in[16];
    const float* iww1  = (const float*)d_in[17];
    const float* iwb1  = (const float*)d_in[18];
    const float* iww2  = (const float*)d_in[19];
    const float* iwb2  = (const float*)d_in[20];
    const float* w_w   = (const float*)d_in[21];
    const float* b_w   = (const float*)d_in[22];

    k_means<<<NB * CIN, 192>>>(x);
    k_conv1<<<NB * 6, 256>>>(w_c1, b_c1);
    k_inv1<<<NB * 4, 256>>>(i1w1, i1b1, i1w2, i1b2, bng, bnb, bnm, bnv);
    k_inv2<<<NB * 2 * 4, 256>>>(ihw1, ihb1, ihw2, ihb2, w_h, b_h,
                                iww1, iwb1, iww2, iwb2, w_w, b_w);
    k_final<<<dim3(9, NB * CIN), 256>>>((const float4*)x, (float4*)d_out);
}

// round 2
// speedup vs baseline: 1.7318x; 1.7318x over previous
#include <cuda_runtime.h>
#include <math.h>

#define NB   16
#define CIN  256
#define MIP  64
#define SEQ  192

// ---- scratch (device globals; no allocation allowed) ----
__device__ float g_y0[NB * CIN * SEQ];    // pooled + concat (b, 256, 192)
__device__ float g_y2[NB * MIP * SEQ];    // after involution1 + BN + hswish
__device__ float g_ah[NB * CIN * 96];     // sigmoid attention (h)
__device__ float g_aw[NB * CIN * 96];     // sigmoid attention (w)
__device__ float g_wt1[CIN * MIP];        // w_c1 transposed [c][o]
__device__ float g_wth[MIP * CIN];        // w_h  transposed [c][o]
__device__ float g_wtw[MIP * CIN];        // w_w  transposed [c][o]
__device__ float g_bnsc[MIP];
__device__ float g_bnsh[MIP];

// ===================== K0: transpose weights + fold BN =====================
// grid = 192 blocks x 256
__global__ void k_prep(const float* __restrict__ wc1,
                       const float* __restrict__ wh,
                       const float* __restrict__ ww,
                       const float* __restrict__ bng, const float* __restrict__ bnb,
                       const float* __restrict__ bnm, const float* __restrict__ bnv) {
    int idx = blockIdx.x * 256 + threadIdx.x;
    if (blockIdx.x == 0 && threadIdx.x < MIP) {
        int t = threadIdx.x;
        float sc = bng[t] * rsqrtf(bnv[t] + 1e-5f);
        g_bnsc[t] = sc;
        g_bnsh[t] = bnb[t] - bnm[t] * sc;
    }
    int m = idx >> 14;          // /16384
    int j = idx & 16383;
    if (m == 0) {               // w_c1: (64 o, 256 c) -> [c][64]
        int o = j >> 8, c = j & 255;
        g_wt1[c * MIP + o] = wc1[j];
    } else if (m == 1) {        // w_h: (256 o, 64 c) -> [c][256]
        int o = j >> 6, c = j & 63;
        g_wth[c * CIN + o] = wh[j];
    } else {                    // w_w
        int o = j >> 6, c = j & 63;
        g_wtw[c * CIN + o] = ww[j];
    }
}

// ===================== K1: row & col means per (b,c) plane =====================
// grid = NB*CIN, block = 256 (8 warps); warp w handles rows [12w, 12w+12)
__global__ void k_means(const float* __restrict__ x) {
    __shared__ float srow[96];
    __shared__ float4 scol4[8][24];
    const int bc   = blockIdx.x;
    const int warp = threadIdx.x >> 5;
    const int lane = threadIdx.x & 31;
    const float4* xp = (const float4*)(x + (size_t)bc * 9216);

    float4 ca = make_float4(0.f, 0.f, 0.f, 0.f);
    #pragma unroll
    for (int k = 0; k < 12; k++) {
        int r = warp * 12 + k;
        float4 v = (lane < 24) ? __ldg(&xp[r * 24 + lane]) : make_float4(0.f, 0.f, 0.f, 0.f);
        ca.x += v.x; ca.y += v.y; ca.z += v.z; ca.w += v.w;
        float rs = (v.x + v.y) + (v.z + v.w);
        #pragma unroll
        for (int off = 16; off; off >>= 1) rs += __shfl_down_sync(0xffffffff, rs, off);
        if (lane == 0) srow[r] = rs;
    }
    if (lane < 24) scol4[warp][lane] = ca;
    __syncthreads();

    int t = threadIdx.x;
    if (t < 96) {               // col mean -> x_w, position 96+t
        float s = 0.f;
        #pragma unroll
        for (int w2 = 0; w2 < 8; w2++) s += ((const float*)scol4[w2])[t];
        g_y0[(size_t)bc * SEQ + 96 + t] = s * (1.f / 96.f);
    } else if (t < 192) {       // row mean -> x_h, position t-96
        g_y0[(size_t)bc * SEQ + (t - 96)] = srow[t - 96] * (1.f / 96.f);
    }
}

// ========== K2: fused conv1x1(256->64) + involution(192) + BN + hswish ==========
// grid = NB*8 (chunks of 24), block = 512
__global__ void k_cinv1(const float* __restrict__ bc1,
                        const float* __restrict__ w1, const float* __restrict__ b1,
                        const float* __restrict__ w2, const float* __restrict__ b2) {
    __shared__ float ys[CIN * 32];      // y0 tile, ps=0..31 <-> gp = p0-3+ps
    __shared__ float y1s[MIP * 36];     // conv output (padded stride 36)
    __shared__ float st[16 * 24];
    __shared__ float sg[28 * 24];

    const int b   = blockIdx.x >> 3;
    const int p0  = (blockIdx.x & 7) * 24;
    const int tid = threadIdx.x;

    // load y0 tile (coalesced along p)
    for (int i = tid; i < CIN * 32; i += 512) {
        int c = i >> 5, ps = i & 31;
        int gp = p0 - 3 + ps;
        ys[i] = (gp >= 0 && gp < SEQ) ? g_y0[((size_t)b * CIN + c) * SEQ + gp] : 0.f;
    }
    __syncthreads();

    // conv1x1: y1[o][ps] for ps in [0,32), o in [0,64)
    {
        const int o  = tid & 63;
        const int pg = tid >> 6;         // 0..7 -> ps = 4*pg..4*pg+3
        float a0 = 0.f, a1 = 0.f, a2 = 0.f, a3 = 0.f;
        const float* wt = g_wt1 + o;
        #pragma unroll 4
        for (int c = 0; c < CIN; c++) {
            float wv = __ldg(wt + c * MIP);
            float4 y4 = *(const float4*)&ys[c * 32 + pg * 4];
            a0 += wv * y4.x; a1 += wv * y4.y; a2 += wv * y4.z; a3 += wv * y4.w;
        }
        float bo = __ldg(bc1 + o);
        float* dst = &y1s[o * 36 + pg * 4];
        dst[0] = a0 + bo; dst[1] = a1 + bo; dst[2] = a2 + bo; dst[3] = a3 + bo;
    }
    __syncthreads();

    // t = w1 @ y1 + b1 (16 x 24)
    if (tid < 384) {
        int r = tid / 24, p = tid % 24;
        float acc = __ldg(b1 + r);
        const float* wr = w1 + r * MIP;
        #pragma unroll 8
        for (int c = 0; c < MIP; c++) acc += __ldg(wr + c) * y1s[c * 36 + 3 + p];
        st[r * 24 + p] = acc;
    }
    __syncthreads();

    // wgt rows k = kh*7+3 per group (28 x 24)
    for (int i = tid; i < 28 * 24; i += 512) {
        int r = i / 24, p = i % 24;
        int g = r / 7, kh = r % 7;
        int row = g * 49 + kh * 7 + 3;
        float acc = __ldg(b2 + row);
        const float* wr = w2 + row * 16;
        #pragma unroll
        for (int c = 0; c < 16; c++) acc += __ldg(wr + c) * st[c * 24 + p];
        sg[i] = acc;
    }
    __syncthreads();

    // involution + BN + hswish
    for (int i = tid; i < MIP * 24; i += 512) {
        int c = i / 24, p = i % 24;
        int g = c >> 4;
        float acc = 0.f;
        #pragma unroll
        for (int kh = 0; kh < 7; kh++)
            acc += sg[(g * 7 + kh) * 24 + p] * y1s[c * 36 + p + kh];
        float v = acc * g_bnsc[c] + g_bnsh[c];
        float hs = v * fminf(fmaxf(v + 3.f, 0.f), 6.f) * (1.f / 6.f);
        g_y2[((size_t)b * MIP + c) * SEQ + p0 + p] = hs;
    }
}

// ========== K3: involution (96-seq, h/w half) + conv1x1 64->256 + sigmoid ==========
// grid = NB*2*4 = 128 (b, half, chunk of 24), block = 512
__global__ void k_inv2(const float* __restrict__ w1h, const float* __restrict__ b1h,
                       const float* __restrict__ w2h, const float* __restrict__ b2h,
                       const float* __restrict__ bch,
                       const float* __restrict__ w1w, const float* __restrict__ b1w,
                       const float* __restrict__ w2w, const float* __restrict__ b2w,
                       const float* __restrict__ bcw) {
    __shared__ float sy[MIP * 32];    // ps = 0..31 <-> gp = p0-3+ps
    __shared__ float st[16 * 24];
    __shared__ float sg[28 * 24];
    __shared__ float sz[MIP * 24];

    const int bid  = blockIdx.x;
    const int b    = bid >> 3;
    const int rest = bid & 7;
    const int half = rest >> 2;
    const int p0   = (rest & 3) * 24;
    const int tid  = threadIdx.x;

    const float* w1 = half ? w1w : w1h;
    const float* b1 = half ? b1w : b1h;
    const float* w2 = half ? w2w : w2h;
    const float* b2 = half ? b2w : b2h;
    const float* bc = half ? bcw : bch;
    const float* wt = half ? g_wtw : g_wth;
    float* outbuf   = half ? g_aw : g_ah;

    for (int i = tid; i < MIP * 32; i += 512) {
        int c = i >> 5, ps = i & 31;
        int gp = p0 - 3 + ps;
        sy[i] = (gp >= 0 && gp < 96)
              ? g_y2[((size_t)b * MIP + c) * SEQ + half * 96 + gp] : 0.f;
    }
    __syncthreads();

    if (tid < 384) {
        int r = tid / 24, p = tid % 24;
        float acc = __ldg(b1 + r);
        const float* wr = w1 + r * MIP;
        #pragma unroll 8
        for (int c = 0; c < MIP; c++) acc += __ldg(wr + c) * sy[c * 32 + 3 + p];
        st[r * 24 + p] = acc;
    }
    __syncthreads();

    for (int i = tid; i < 28 * 24; i += 512) {
        int r = i / 24, p = i % 24;
        int g = r / 7, kh = r % 7;
        int row = half ? (g * 49 + 21 + kh) : (g * 49 + kh * 7 + 3);
        float acc = __ldg(b2 + row);
        const float* wr = w2 + row * 16;
        #pragma unroll
        for (int c = 0; c < 16; c++) acc += __ldg(wr + c) * st[c * 24 + p];
        sg[i] = acc;
    }
    __syncthreads();

    for (int i = tid; i < MIP * 24; i += 512) {
        int c = i / 24, p = i % 24;
        int g = c >> 4;
        float acc = 0.f;
        #pragma unroll
        for (int kh = 0; kh < 7; kh++)
            acc += sg[(g * 7 + kh) * 24 + p] * sy[c * 32 + p + kh];
        sz[c * 24 + p] = acc;
    }
    __syncthreads();

    // conv 64 -> 256 + sigmoid: thread = (og, q); 12 positions each
    {
        const int og = tid >> 1;     // 0..255
        const int q  = tid & 1;      // 0..1 -> p = q*12 + j
        float acc[12];
        #pragma unroll
        for (int j = 0; j < 12; j++) acc[j] = 0.f;
        const float* wp = wt + og;
        #pragma unroll 4
        for (int c = 0; c < MIP; c++) {
            float wv = __ldg(wp + c * CIN);
            const float* zb = &sz[c * 24 + q * 12];
            float4 z0 = *(const float4*)(zb);
            float4 z1 = *(const float4*)(zb + 4);
            float4 z2 = *(const float4*)(zb + 8);
            acc[0] += wv * z0.x; acc[1] += wv * z0.y; acc[2]  += wv * z0.z; acc[3]  += wv * z0.w;
            acc[4] += wv * z1.x; acc[5] += wv * z1.y; acc[6]  += wv * z1.z; acc[7]  += wv * z1.w;
            acc[8] += wv * z2.x; acc[9] += wv * z2.y; acc[10] += wv * z2.z; acc[11] += wv * z2.w;
        }
        float bo = __ldg(bc + og);
        float* op = outbuf + ((size_t)b * CIN + og) * 96 + p0 + q * 12;
        #pragma unroll
        for (int j = 0; j < 12; j++) {
            float v = acc[j] + bo;
            op[j] = 1.f / (1.f + __expf(-v));
        }
    }
}

// ===================== K4: out = x * a_h * a_w (float4) =====================
// grid = (9, NB*CIN), block = 256; plane = 96*24 float4
__global__ void k_final(const float4* __restrict__ x, float4* __restrict__ out) {
    int t = blockIdx.x * 256 + threadIdx.x;
    if (t >= 96 * 24) return;
    int bc = blockIdx.y;
    int i  = t / 24;
    int jf = t % 24;
    float h = __ldg(g_ah + (size_t)bc * 96 + i);
    const float4* aw4 = (const float4*)g_aw;
    float4 wv = __ldg(aw4 + (size_t)bc * 24 + jf);
    size_t idx = (size_t)bc * (96 * 24) + t;
    float4 xv = __ldg(x + idx);
    float4 r;
    r.x = xv.x * h * wv.x;
    r.y = xv.y * h * wv.y;
    r.z = xv.z * h * wv.z;
    r.w = xv.w * h * wv.w;
    out[idx] = r;
}

// ===================== launch =====================
extern "C" void kernel_launch(void* const* d_in, const int* in_sizes, int n_in,
                              void* d_out, int out_size) {
    const float* x     = (const float*)d_in[0];
    const float* w_c1  = (const float*)d_in[1];
    const float* b_c1  = (const float*)d_in[2];
    const float* i1w1  = (const float*)d_in[3];
    const float* i1b1  = (const float*)d_in[4];
    const float* i1w2  = (const float*)d_in[5];
    const float* i1b2  = (const float*)d_in[6];
    const float* bng   = (const float*)d_in[7];
    const float* bnb   = (const float*)d_in[8];
    const float* bnm   = (const float*)d_in[9];
    const float* bnv   = (const float*)d_in[10];
    const float* ihw1  = (const float*)d_in[11];
    const float* ihb1  = (const float*)d_in[12];
    const float* ihw2  = (const float*)d_in[13];
    const float* ihb2  = (const float*)d_in[14];
    const float* w_h   = (const float*)d_in[15];
    const float* b_h   = (const float*)d_in[16];
    const float* iww1  = (const float*)d_in[17];
    const float* iwb1  = (const float*)d_in[18];
    const float* iww2  = (const float*)d_in[19];
    const float* iwb2  = (const float*)d_in[20];
    const float* w_w   = (const float*)d_in[21];
    const float* b_w   = (const float*)d_in[22];

    k_prep<<<192, 256>>>(w_c1, w_h, w_w, bng, bnb, bnm, bnv);
    k_means<<<NB * CIN, 256>>>(x);
    k_cinv1<<<NB * 8, 512>>>(b_c1, i1w1, i1b1, i1w2, i1b2);
    k_inv2<<<NB * 2 * 4, 512>>>(ihw1, ihb1, ihw2, ihb2, b_h,
                                iww1, iwb1, iww2, iwb2, b_w);
    k_final<<<dim3(9, NB * CIN), 256>>>((const float4*)x, (float4*)d_out);
}

// round 3
// speedup vs baseline: 2.0859x; 1.2045x over previous
#include <cuda_runtime.h>
#include <math.h>

#define NB   16
#define CIN  256
#define MIP  64
#define SEQ  192

// ---- scratch (device globals; no allocation allowed) ----
__device__ float g_y0[NB * CIN * SEQ];    // pooled + concat (b, 256, 192)
__device__ float g_y2[NB * MIP * SEQ];    // after involution1 + BN + hswish
__device__ float g_ah[NB * CIN * 96];     // sigmoid attention (h)
__device__ float g_aw[NB * CIN * 96];     // sigmoid attention (w)

// ---------------- helpers ----------------
__device__ __forceinline__ void cp_async4(void* smem_dst, const void* gmem_src) {
    unsigned s = (unsigned)__cvta_generic_to_shared(smem_dst);
    asm volatile("cp.async.ca.shared.global [%0], [%1], 4;" :: "r"(s), "l"(gmem_src));
}
__device__ __forceinline__ void cp_commit() {
    asm volatile("cp.async.commit_group;");
}
__device__ __forceinline__ void cp_wait0() {
    asm volatile("cp.async.wait_group 0;" ::: "memory");
}
__device__ __forceinline__ void cp_wait1() {
    asm volatile("cp.async.wait_group 1;" ::: "memory");
}
__device__ __forceinline__ unsigned long long pack2(float a, float b) {
    unsigned long long r;
    asm("mov.b64 %0, {%1, %2};" : "=l"(r) : "f"(a), "f"(b));
    return r;
}
__device__ __forceinline__ unsigned long long ffma2(unsigned long long a,
                                                    unsigned long long b,
                                                    unsigned long long c) {
    unsigned long long d;
    asm("fma.rn.f32x2 %0, %1, %2, %3;" : "=l"(d) : "l"(a), "l"(b), "l"(c));
    return d;
}
__device__ __forceinline__ void unpack2(unsigned long long v, float& lo, float& hi) {
    asm("mov.b64 {%0, %1}, %2;" : "=f"(lo), "=f"(hi) : "l"(v));
}

// ===================== K1: row & col means per (b,c) plane =====================
// grid = NB*CIN, block = 256 (8 warps); warp w handles rows [12w, 12w+12)
__global__ void k_means(const float* __restrict__ x) {
    __shared__ float srow[96];
    __shared__ float4 scol4[8][24];
    const int bc   = blockIdx.x;
    const int warp = threadIdx.x >> 5;
    const int lane = threadIdx.x & 31;
    const float4* xp = (const float4*)(x + (size_t)bc * 9216);

    float4 ca = make_float4(0.f, 0.f, 0.f, 0.f);
    #pragma unroll
    for (int k = 0; k < 12; k++) {
        int r = warp * 12 + k;
        float4 v = (lane < 24) ? __ldg(&xp[r * 24 + lane]) : make_float4(0.f, 0.f, 0.f, 0.f);
        ca.x += v.x; ca.y += v.y; ca.z += v.z; ca.w += v.w;
        float rs = (v.x + v.y) + (v.z + v.w);
        #pragma unroll
        for (int off = 16; off; off >>= 1) rs += __shfl_down_sync(0xffffffff, rs, off);
        if (lane == 0) srow[r] = rs;
    }
    if (lane < 24) scol4[warp][lane] = ca;
    __syncthreads();

    int t = threadIdx.x;
    if (t < 96) {               // col mean -> x_w, position 96+t
        float s = 0.f;
        #pragma unroll
        for (int w2 = 0; w2 < 8; w2++) s += ((const float*)scol4[w2])[t];
        g_y0[(size_t)bc * SEQ + 96 + t] = s * (1.f / 96.f);
    } else if (t < 192) {       // row mean -> x_h, position t-96
        g_y0[(size_t)bc * SEQ + (t - 96)] = srow[t - 96] * (1.f / 96.f);
    }
}

// ========== K2: fused conv1x1(256->64) + involution(192) + BN + hswish ==========
// grid = NB*8 (chunks of 24), block = 512, dynamic smem
// smem layout (floats):
//   sw1  [64*257]  = 16448   (w_c1, pad-257)
//   sww1 [16*64]   = 1024
//   sb1  [16]
//   sw2  [196*16]  = 3136
//   sb2  [196]
//   sbc1 [64]
//   sbn  [256]               (bng | bnb | bnm | bnv)
//   ys   [256*32]  = 8192
//   y1s  [64*37]   = 2368
//   st   [16*24]   = 384
//   sg   [28*24]   = 672
#define C1_SMEM_FLOATS 32756
__global__ void __launch_bounds__(512, 1)
k_cinv1(const float* __restrict__ wc1, const float* __restrict__ bc1,
        const float* __restrict__ w1, const float* __restrict__ b1,
        const float* __restrict__ w2, const float* __restrict__ b2,
        const float* __restrict__ bng, const float* __restrict__ bnb,
        const float* __restrict__ bnm, const float* __restrict__ bnv) {
    extern __shared__ float dyn[];
    float* sw1  = dyn;                 // 16448
    float* sww1 = sw1  + 16448;        // 1024
    float* sb1  = sww1 + 1024;         // 16
    float* sw2  = sb1  + 16;           // 3136
    float* sb2  = sw2  + 3136;         // 196
    float* sbc1 = sb2  + 196;          // 64
    float* sbn  = sbc1 + 64;           // 256
    float* ys   = sbn  + 256;          // 8192
    float* y1s  = ys   + 8192;         // 2368
    float* st   = y1s  + 2368;         // 384
    float* sg   = st   + 384;          // 672

    const int b   = blockIdx.x >> 3;
    const int p0  = (blockIdx.x & 7) * 24;
    const int tid = threadIdx.x;

    // ---- stage all weights via cp.async ----
    for (int i = tid; i < 64 * 256; i += 512)
        cp_async4(&sw1[(i >> 8) * 257 + (i & 255)], wc1 + i);
    for (int i = tid; i < 1024; i += 512) cp_async4(&sww1[i], w1 + i);
    if (tid < 16)  cp_async4(&sb1[tid], b1 + tid);
    for (int i = tid; i < 3136; i += 512) cp_async4(&sw2[i], w2 + i);
    if (tid < 196) cp_async4(&sb2[tid], b2 + tid);
    if (tid < 64)  cp_async4(&sbc1[tid], bc1 + tid);
    if (tid < 64)        cp_async4(&sbn[tid],       bng + tid);
    else if (tid < 128)  cp_async4(&sbn[tid],       bnb + tid - 64);
    else if (tid < 192)  cp_async4(&sbn[tid],       bnm + tid - 128);
    else if (tid < 256)  cp_async4(&sbn[tid],       bnv + tid - 192);
    cp_commit();

    // ---- load y0 tile (regular loads, overlap with cp.async) ----
    for (int i = tid; i < CIN * 32; i += 512) {
        int c = i >> 5, ps = i & 31;
        int gp = p0 - 3 + ps;
        ys[i] = (gp >= 0 && gp < SEQ) ? g_y0[((size_t)b * CIN + c) * SEQ + gp] : 0.f;
    }
    cp_wait0();
    __syncthreads();

    // ---- conv1x1 (packed f32x2): y1[o][ps], 64 o x 32 ps ----
    {
        const int o  = tid & 63;
        const int pg = tid >> 6;       // 0..7 -> ps = 4*pg .. 4*pg+3
        unsigned long long a0 = 0ull, a1 = 0ull;
        #pragma unroll 8
        for (int c = 0; c < CIN; c++) {
            float wv = sw1[o * 257 + c];
            unsigned long long wp = pack2(wv, wv);
            longlong2 y = *(const longlong2*)&ys[c * 32 + pg * 4];
            a0 = ffma2(wp, (unsigned long long)y.x, a0);
            a1 = ffma2(wp, (unsigned long long)y.y, a1);
        }
        float v0, v1, v2, v3;
        unpack2(a0, v0, v1); unpack2(a1, v2, v3);
        float bo = sbc1[o];
        float* dst = &y1s[o * 37 + pg * 4];
        int gbase = p0 - 3 + pg * 4;
        dst[0] = (gbase + 0 >= 0 && gbase + 0 < SEQ) ? v0 + bo : 0.f;
        dst[1] = (gbase + 1 >= 0 && gbase + 1 < SEQ) ? v1 + bo : 0.f;
        dst[2] = (gbase + 2 >= 0 && gbase + 2 < SEQ) ? v2 + bo : 0.f;
        dst[3] = (gbase + 3 >= 0 && gbase + 3 < SEQ) ? v3 + bo : 0.f;
    }
    __syncthreads();

    // ---- t = w1 @ y1 + b1 (16 x 24) ----
    if (tid < 384) {
        int r = tid / 24, p = tid % 24;
        float acc = sb1[r];
        const float* wr = &sww1[r * 64];
        #pragma unroll 8
        for (int c = 0; c < MIP; c++) acc += wr[c] * y1s[c * 37 + 3 + p];
        st[r * 24 + p] = acc;
    }
    __syncthreads();

    // ---- wgt rows k = kh*7+3 per group (28 x 24) ----
    for (int i = tid; i < 28 * 24; i += 512) {
        int r = i / 24, p = i % 24;
        int g = r / 7, kh = r % 7;
        int row = g * 49 + kh * 7 + 3;
        float acc = sb2[row];
        const float* wr = &sw2[row * 16];
        #pragma unroll
        for (int c = 0; c < 16; c++) acc += wr[c] * st[c * 24 + p];
        sg[i] = acc;
    }
    __syncthreads();

    // ---- involution + BN + hswish ----
    for (int i = tid; i < MIP * 24; i += 512) {
        int c = i / 24, p = i % 24;
        int g = c >> 4;
        float acc = 0.f;
        #pragma unroll
        for (int kh = 0; kh < 7; kh++)
            acc += sg[(g * 7 + kh) * 24 + p] * y1s[c * 37 + p + kh];
        float sc = sbn[c] * rsqrtf(sbn[192 + c] + 1e-5f);
        float v  = (acc - sbn[128 + c]) * sc + sbn[64 + c];
        float hs = v * fminf(fmaxf(v + 3.f, 0.f), 6.f) * (1.f / 6.f);
        g_y2[((size_t)b * MIP + c) * SEQ + p0 + p] = hs;
    }
}

// ========== K3: involution (96-seq, h/w half) + conv1x1 64->256 + sigmoid ==========
// grid = NB*2*4 = 128, block = 512, dynamic smem
// smem layout (floats):
//   sw   [256*65] = 16640   (conv weight, pad-65)
//   sww1 [1024], sb1 [16], sw2 [3136], sb2 [196], sbc [256]
//   sy   [64*32] = 2048, st [384], sg [672], sz [64*24] = 1536
#define C2_SMEM_FLOATS 25908
__global__ void __launch_bounds__(512, 2)
k_inv2(const float* __restrict__ w1h, const float* __restrict__ b1h,
       const float* __restrict__ w2h, const float* __restrict__ b2h,
       const float* __restrict__ wch, const float* __restrict__ bch,
       const float* __restrict__ w1w, const float* __restrict__ b1w,
       const float* __restrict__ w2w, const float* __restrict__ b2w,
       const float* __restrict__ wcw, const float* __restrict__ bcw) {
    extern __shared__ float dyn[];
    float* sw   = dyn;               // 16640
    float* sww1 = sw   + 16640;      // 1024
    float* sb1  = sww1 + 1024;       // 16
    float* sw2  = sb1  + 16;         // 3136
    float* sb2  = sw2  + 3136;       // 196
    float* sbc  = sb2  + 196;        // 256
    float* sy   = sbc  + 256;        // 2048
    float* st   = sy   + 2048;       // 384
    float* sg   = st   + 384;        // 672
    float* sz   = sg   + 672;        // 1536

    const int bid  = blockIdx.x;
    const int b    = bid >> 3;
    const int rest = bid & 7;
    const int half = rest >> 2;
    const int p0   = (rest & 3) * 24;
    const int tid  = threadIdx.x;

    const float* w1 = half ? w1w : w1h;
    const float* b1 = half ? b1w : b1h;
    const float* w2 = half ? w2w : w2h;
    const float* b2 = half ? b2w : b2h;
    const float* wc = half ? wcw : wch;
    const float* bc = half ? bcw : bch;
    float* outbuf   = half ? g_aw : g_ah;

    // ---- group A: small arrays (needed by early phases) ----
    for (int i = tid; i < 1024; i += 512) cp_async4(&sww1[i], w1 + i);
    if (tid < 16)  cp_async4(&sb1[tid], b1 + tid);
    for (int i = tid; i < 3136; i += 512) cp_async4(&sw2[i], w2 + i);
    if (tid < 196) cp_async4(&sb2[tid], b2 + tid);
    if (tid < 256) cp_async4(&sbc[tid], bc + tid);
    cp_commit();
    // ---- group B: big conv weight (needed only at the end) ----
    for (int i = tid; i < CIN * MIP; i += 512)
        cp_async4(&sw[(i >> 6) * 65 + (i & 63)], wc + i);
    cp_commit();

    // ---- load y2 half-tile ----
    for (int i = tid; i < MIP * 32; i += 512) {
        int c = i >> 5, ps = i & 31;
        int gp = p0 - 3 + ps;
        sy[i] = (gp >= 0 && gp < 96)
              ? g_y2[((size_t)b * MIP + c) * SEQ + half * 96 + gp] : 0.f;
    }
    cp_wait1();     // group A done
    __syncthreads();

    // ---- t = w1 @ y + b1 (16 x 24) ----
    if (tid < 384) {
        int r = tid / 24, p = tid % 24;
        float acc = sb1[r];
        const float* wr = &sww1[r * 64];
        #pragma unroll 8
        for (int c = 0; c < MIP; c++) acc += wr[c] * sy[c * 32 + 3 + p];
        st[r * 24 + p] = acc;
    }
    __syncthreads();

    // ---- wgt rows (28 x 24) ----
    for (int i = tid; i < 28 * 24; i += 512) {
        int r = i / 24, p = i % 24;
        int g = r / 7, kh = r % 7;
        int row = half ? (g * 49 + 21 + kh) : (g * 49 + kh * 7 + 3);
        float acc = sb2[row];
        const float* wr = &sw2[row * 16];
        #pragma unroll
        for (int c = 0; c < 16; c++) acc += wr[c] * st[c * 24 + p];
        sg[i] = acc;
    }
    __syncthreads();

    // ---- involution (64 x 24) ----
    for (int i = tid; i < MIP * 24; i += 512) {
        int c = i / 24, p = i % 24;
        int g = c >> 4;
        float acc = 0.f;
        #pragma unroll
        for (int kh = 0; kh < 7; kh++)
            acc += sg[(g * 7 + kh) * 24 + p] * sy[c * 32 + p + kh];
        sz[c * 24 + p] = acc;
    }
    cp_wait0();     // group B (conv weights) done
    __syncthreads();

    // ---- conv 64 -> 256 + sigmoid (packed f32x2); thread = (og, q), 12 pos ----
    {
        const int og = tid >> 1;     // 0..255
        const int q  = tid & 1;      // p = q*12 + j
        unsigned long long acc[6];
        #pragma unroll
        for (int k = 0; k < 6; k++) acc[k] = 0ull;
        #pragma unroll 4
        for (int c = 0; c < MIP; c++) {
            float wv = sw[og * 65 + c];
            unsigned long long wp = pack2(wv, wv);
            const longlong2* zp = (const longlong2*)&sz[c * 24 + q * 12];
            longlong2 za = zp[0];
            longlong2 zb = zp[1];
            longlong2 zc = zp[2];
            acc[0] = ffma2(wp, (unsigned long long)za.x, acc[0]);
            acc[1] = ffma2(wp, (unsigned long long)za.y, acc[1]);
            acc[2] = ffma2(wp, (unsigned long long)zb.x, acc[2]);
            acc[3] = ffma2(wp, (unsigned long long)zb.y, acc[3]);
            acc[4] = ffma2(wp, (unsigned long long)zc.x, acc[4]);
            acc[5] = ffma2(wp, (unsigned long long)zc.y, acc[5]);
        }
        float bo = sbc[og];
        float* op = outbuf + ((size_t)b * CIN + og) * 96 + p0 + q * 12;
        #pragma unroll
        for (int k = 0; k < 6; k++) {
            float lo, hi;
            unpack2(acc[k], lo, hi);
            float v0 = lo + bo, v1 = hi + bo;
            op[2 * k]     = 1.f / (1.f + __expf(-v0));
            op[2 * k + 1] = 1.f / (1.f + __expf(-v1));
        }
    }
}

// ===================== K4: out = x * a_h * a_w (float4) =====================
// grid = (9, NB*CIN), block = 256; plane = 96*24 float4
__global__ void k_final(const float4* __restrict__ x, float4* __restrict__ out) {
    int t = blockIdx.x * 256 + threadIdx.x;
    if (t >= 96 * 24) return;
    int bc = blockIdx.y;
    int i  = t / 24;
    int jf = t % 24;
    float h = __ldg(g_ah + (size_t)bc * 96 + i);
    const float4* aw4 = (const float4*)g_aw;
    float4 wv = __ldg(aw4 + (size_t)bc * 24 + jf);
    size_t idx = (size_t)bc * (96 * 24) + t;
    float4 xv = __ldg(x + idx);
    float4 r;
    r.x = xv.x * h * wv.x;
    r.y = xv.y * h * wv.y;
    r.z = xv.z * h * wv.z;
    r.w = xv.w * h * wv.w;
    out[idx] = r;
}

// ===================== launch =====================
extern "C" void kernel_launch(void* const* d_in, const int* in_sizes, int n_in,
                              void* d_out, int out_size) {
    const float* x     = (const float*)d_in[0];
    const float* w_c1  = (const float*)d_in[1];
    const float* b_c1  = (const float*)d_in[2];
    const float* i1w1  = (const float*)d_in[3];
    const float* i1b1  = (const float*)d_in[4];
    const float* i1w2  = (const float*)d_in[5];
    const float* i1b2  = (const float*)d_in[6];
    const float* bng   = (const float*)d_in[7];
    const float* bnb   = (const float*)d_in[8];
    const float* bnm   = (const float*)d_in[9];
    const float* bnv   = (const float*)d_in[10];
    const float* ihw1  = (const float*)d_in[11];
    const float* ihb1  = (const float*)d_in[12];
    const float* ihw2  = (const float*)d_in[13];
    const float* ihb2  = (const float*)d_in[14];
    const float* w_h   = (const float*)d_in[15];
    const float* b_h   = (const float*)d_in[16];
    const float* iww1  = (const float*)d_in[17];
    const float* iwb1  = (const float*)d_in[18];
    const float* iww2  = (const float*)d_in[19];
    const float* iwb2  = (const float*)d_in[20];
    const float* w_w   = (const float*)d_in[21];
    const float* b_w   = (const float*)d_in[22];

    static bool attr_done = false;
    cudaFuncSetAttribute(k_cinv1, cudaFuncAttributeMaxDynamicSharedMemorySize,
                         C1_SMEM_FLOATS * 4);
    cudaFuncSetAttribute(k_inv2, cudaFuncAttributeMaxDynamicSharedMemorySize,
                         C2_SMEM_FLOATS * 4);
    (void)attr_done;

    k_means<<<NB * CIN, 256>>>(x);
    k_cinv1<<<NB * 8, 512, C1_SMEM_FLOATS * 4>>>(w_c1, b_c1, i1w1, i1b1, i1w2, i1b2,
                                                 bng, bnb, bnm, bnv);
    k_inv2<<<NB * 2 * 4, 512, C2_SMEM_FLOATS * 4>>>(ihw1, ihb1, ihw2, ihb2, w_h, b_h,
                                                    iww1, iwb1, iww2, iwb2, w_w, b_w);
    k_final<<<dim3(9, NB * CIN), 256>>>((const float4*)x, (float4*)d_out);
}

// round 4
// speedup vs baseline: 2.2576x; 1.0823x over previous
#include <cuda_runtime.h>
#include <math.h>

#define NB   16
#define CIN  256
#define MIP  64
#define SEQ  192

// ---- scratch (device globals; no allocation allowed) ----
__device__ float g_y0[NB * CIN * SEQ];    // pooled + concat (b, 256, 192)
__device__ float g_y2[NB * MIP * SEQ];    // after involution1 + BN + hswish
__device__ float g_ah[NB * CIN * 96];     // sigmoid attention (h)
__device__ float g_aw[NB * CIN * 96];     // sigmoid attention (w)

// ---------------- helpers ----------------
__device__ __forceinline__ void cp_async4(void* smem_dst, const void* gmem_src) {
    unsigned s = (unsigned)__cvta_generic_to_shared(smem_dst);
    asm volatile("cp.async.ca.shared.global [%0], [%1], 4;" :: "r"(s), "l"(gmem_src));
}
__device__ __forceinline__ void cp_commit() {
    asm volatile("cp.async.commit_group;");
}
__device__ __forceinline__ void cp_wait0() {
    asm volatile("cp.async.wait_group 0;" ::: "memory");
}
__device__ __forceinline__ void cp_wait1() {
    asm volatile("cp.async.wait_group 1;" ::: "memory");
}
__device__ __forceinline__ unsigned long long pack2(float a, float b) {
    unsigned long long r;
    asm("mov.b64 %0, {%1, %2};" : "=l"(r) : "f"(a), "f"(b));
    return r;
}
__device__ __forceinline__ unsigned long long ffma2(unsigned long long a,
                                                    unsigned long long b,
                                                    unsigned long long c) {
    unsigned long long d;
    asm("fma.rn.f32x2 %0, %1, %2, %3;" : "=l"(d) : "l"(a), "l"(b), "l"(c));
    return d;
}
__device__ __forceinline__ void unpack2(unsigned long long v, float& lo, float& hi) {
    asm("mov.b64 {%0, %1}, %2;" : "=f"(lo), "=f"(hi) : "l"(v));
}

// ===================== K1: row & col means per (b,c) plane =====================
// grid = NB*CIN, block = 256. Stage plane in smem (9 coalesced float4 LDGs per
// thread, MLP=9), then 96 row-sum threads + 96 col-sum threads. No shuffles.
__global__ void k_means(const float* __restrict__ x) {
    __shared__ float4 sp4[96 * 25];     // row stride 25 float4 (pad)
    const int bc  = blockIdx.x;
    const int tid = threadIdx.x;
    const float4* xp = (const float4*)(x + (size_t)bc * 9216);

    float4 v[9];
    #pragma unroll
    for (int k = 0; k < 9; k++) v[k] = __ldg(&xp[tid + k * 256]);
    #pragma unroll
    for (int k = 0; k < 9; k++) {
        int i = tid + k * 256;
        int r = i / 24, c4 = i % 24;
        sp4[r * 25 + c4] = v[k];
    }
    __syncthreads();

    if (tid < 96) {
        // row mean (x_h), position tid
        const float4* rp = &sp4[tid * 25];
        float4 a = make_float4(0.f, 0.f, 0.f, 0.f);
        #pragma unroll 6
        for (int j = 0; j < 24; j++) {
            float4 q = rp[j];
            a.x += q.x; a.y += q.y; a.z += q.z; a.w += q.w;
        }
        float s = (a.x + a.y) + (a.z + a.w);
        g_y0[(size_t)bc * SEQ + tid] = s * (1.f / 96.f);
    } else if (tid < 192) {
        // col mean (x_w), position 96 + c
        int c = tid - 96;
        const float* spf = (const float*)sp4;    // row stride 100 floats
        float s0 = 0.f, s1 = 0.f, s2 = 0.f, s3 = 0.f;
        #pragma unroll 8
        for (int r = 0; r < 96; r += 4) {
            s0 += spf[(r + 0) * 100 + c];
            s1 += spf[(r + 1) * 100 + c];
            s2 += spf[(r + 2) * 100 + c];
            s3 += spf[(r + 3) * 100 + c];
        }
        g_y0[(size_t)bc * SEQ + 96 + c] = ((s0 + s1) + (s2 + s3)) * (1.f / 96.f);
    }
}

// ========== K2: fused conv1x1(256->64) + involution(192) + BN + hswish ==========
// grid = NB*8 (chunks of 24), block = 512, dynamic smem
#define C1_SMEM_FLOATS 32756
__global__ void __launch_bounds__(512, 1)
k_cinv1(const float* __restrict__ wc1, const float* __restrict__ bc1,
        const float* __restrict__ w1, const float* __restrict__ b1,
        const float* __restrict__ w2, const float* __restrict__ b2,
        const float* __restrict__ bng, const float* __restrict__ bnb,
        const float* __restrict__ bnm, const float* __restrict__ bnv) {
    extern __shared__ float dyn[];
    float* sw1  = dyn;                 // 16448 (64 x pad257)
    float* sww1 = sw1  + 16448;        // 1024
    float* sb1  = sww1 + 1024;         // 16
    float* sw2  = sb1  + 16;           // 3136
    float* sb2  = sw2  + 3136;         // 196
    float* sbc1 = sb2  + 196;          // 64
    float* sbn  = sbc1 + 64;           // 256
    float* ys   = sbn  + 256;          // 8192 (256 x 32)
    float* y1s  = ys   + 8192;         // 2368 (64 x pad37)
    float* st   = y1s  + 2368;         // 384
    float* sg   = st   + 384;          // 672

    const int b   = blockIdx.x >> 3;
    const int p0  = (blockIdx.x & 7) * 24;
    const int tid = threadIdx.x;

    for (int i = tid; i < 64 * 256; i += 512)
        cp_async4(&sw1[(i >> 8) * 257 + (i & 255)], wc1 + i);
    for (int i = tid; i < 1024; i += 512) cp_async4(&sww1[i], w1 + i);
    if (tid < 16)  cp_async4(&sb1[tid], b1 + tid);
    for (int i = tid; i < 3136; i += 512) cp_async4(&sw2[i], w2 + i);
    if (tid < 196) cp_async4(&sb2[tid], b2 + tid);
    if (tid < 64)  cp_async4(&sbc1[tid], bc1 + tid);
    if (tid < 64)        cp_async4(&sbn[tid], bng + tid);
    else if (tid < 128)  cp_async4(&sbn[tid], bnb + tid - 64);
    else if (tid < 192)  cp_async4(&sbn[tid], bnm + tid - 128);
    else if (tid < 256)  cp_async4(&sbn[tid], bnv + tid - 192);
    cp_commit();

    for (int i = tid; i < CIN * 32; i += 512) {
        int c = i >> 5, ps = i & 31;
        int gp = p0 - 3 + ps;
        ys[i] = (gp >= 0 && gp < SEQ) ? g_y0[((size_t)b * CIN + c) * SEQ + gp] : 0.f;
    }
    cp_wait0();
    __syncthreads();

    // conv1x1 (packed f32x2): y1[o][ps], 64 o x 32 ps
    {
        const int o  = tid & 63;
        const int pg = tid >> 6;
        unsigned long long a0 = 0ull, a1 = 0ull;
        #pragma unroll 8
        for (int c = 0; c < CIN; c++) {
            float wv = sw1[o * 257 + c];
            unsigned long long wp = pack2(wv, wv);
            longlong2 y = *(const longlong2*)&ys[c * 32 + pg * 4];
            a0 = ffma2(wp, (unsigned long long)y.x, a0);
            a1 = ffma2(wp, (unsigned long long)y.y, a1);
        }
        float v0, v1, v2, v3;
        unpack2(a0, v0, v1); unpack2(a1, v2, v3);
        float bo = sbc1[o];
        float* dst = &y1s[o * 37 + pg * 4];
        int gbase = p0 - 3 + pg * 4;
        dst[0] = (gbase + 0 >= 0 && gbase + 0 < SEQ) ? v0 + bo : 0.f;
        dst[1] = (gbase + 1 >= 0 && gbase + 1 < SEQ) ? v1 + bo : 0.f;
        dst[2] = (gbase + 2 >= 0 && gbase + 2 < SEQ) ? v2 + bo : 0.f;
        dst[3] = (gbase + 3 >= 0 && gbase + 3 < SEQ) ? v3 + bo : 0.f;
    }
    __syncthreads();

    if (tid < 384) {
        int r = tid / 24, p = tid % 24;
        float acc = sb1[r];
        const float* wr = &sww1[r * 64];
        #pragma unroll 8
        for (int c = 0; c < MIP; c++) acc += wr[c] * y1s[c * 37 + 3 + p];
        st[r * 24 + p] = acc;
    }
    __syncthreads();

    for (int i = tid; i < 28 * 24; i += 512) {
        int r = i / 24, p = i % 24;
        int g = r / 7, kh = r % 7;
        int row = g * 49 + kh * 7 + 3;
        float acc = sb2[row];
        const float* wr = &sw2[row * 16];
        #pragma unroll
        for (int c = 0; c < 16; c++) acc += wr[c] * st[c * 24 + p];
        sg[i] = acc;
    }
    __syncthreads();

    for (int i = tid; i < MIP * 24; i += 512) {
        int c = i / 24, p = i % 24;
        int g = c >> 4;
        float acc = 0.f;
        #pragma unroll
        for (int kh = 0; kh < 7; kh++)
            acc += sg[(g * 7 + kh) * 24 + p] * y1s[c * 37 + p + kh];
        float sc = sbn[c] * rsqrtf(sbn[192 + c] + 1e-5f);
        float v  = (acc - sbn[128 + c]) * sc + sbn[64 + c];
        float hs = v * fminf(fmaxf(v + 3.f, 0.f), 6.f) * (1.f / 6.f);
        g_y2[((size_t)b * MIP + c) * SEQ + p0 + p] = hs;
    }
}

// ========== K3: involution (96-seq, h/w half) + conv1x1 64->256 + sigmoid ==========
#define C2_SMEM_FLOATS 25908
__global__ void __launch_bounds__(512, 2)
k_inv2(const float* __restrict__ w1h, const float* __restrict__ b1h,
       const float* __restrict__ w2h, const float* __restrict__ b2h,
       const float* __restrict__ wch, const float* __restrict__ bch,
       const float* __restrict__ w1w, const float* __restrict__ b1w,
       const float* __restrict__ w2w, const float* __restrict__ b2w,
       const float* __restrict__ wcw, const float* __restrict__ bcw) {
    extern __shared__ float dyn[];
    float* sw   = dyn;               // 16640 (256 x pad65)
    float* sww1 = sw   + 16640;      // 1024
    float* sb1  = sww1 + 1024;       // 16
    float* sw2  = sb1  + 16;         // 3136
    float* sb2  = sw2  + 3136;       // 196
    float* sbc  = sb2  + 196;        // 256
    float* sy   = sbc  + 256;        // 2048
    float* st   = sy   + 2048;       // 384
    float* sg   = st   + 384;        // 672
    float* sz   = sg   + 672;        // 1536

    const int bid  = blockIdx.x;
    const int b    = bid >> 3;
    const int rest = bid & 7;
    const int half = rest >> 2;
    const int p0   = (rest & 3) * 24;
    const int tid  = threadIdx.x;

    const float* w1 = half ? w1w : w1h;
    const float* b1 = half ? b1w : b1h;
    const float* w2 = half ? w2w : w2h;
    const float* b2 = half ? b2w : b2h;
    const float* wc = half ? wcw : wch;
    const float* bc = half ? bcw : bch;
    float* outbuf   = half ? g_aw : g_ah;

    for (int i = tid; i < 1024; i += 512) cp_async4(&sww1[i], w1 + i);
    if (tid < 16)  cp_async4(&sb1[tid], b1 + tid);
    for (int i = tid; i < 3136; i += 512) cp_async4(&sw2[i], w2 + i);
    if (tid < 196) cp_async4(&sb2[tid], b2 + tid);
    if (tid < 256) cp_async4(&sbc[tid], bc + tid);
    cp_commit();
    for (int i = tid; i < CIN * MIP; i += 512)
        cp_async4(&sw[(i >> 6) * 65 + (i & 63)], wc + i);
    cp_commit();

    for (int i = tid; i < MIP * 32; i += 512) {
        int c = i >> 5, ps = i & 31;
        int gp = p0 - 3 + ps;
        sy[i] = (gp >= 0 && gp < 96)
              ? g_y2[((size_t)b * MIP + c) * SEQ + half * 96 + gp] : 0.f;
    }
    cp_wait1();
    __syncthreads();

    if (tid < 384) {
        int r = tid / 24, p = tid % 24;
        float acc = sb1[r];
        const float* wr = &sww1[r * 64];
        #pragma unroll 8
        for (int c = 0; c < MIP; c++) acc += wr[c] * sy[c * 32 + 3 + p];
        st[r * 24 + p] = acc;
    }
    __syncthreads();

    for (int i = tid; i < 28 * 24; i += 512) {
        int r = i / 24, p = i % 24;
        int g = r / 7, kh = r % 7;
        int row = half ? (g * 49 + 21 + kh) : (g * 49 + kh * 7 + 3);
        float acc = sb2[row];
        const float* wr = &sw2[row * 16];
        #pragma unroll
        for (int c = 0; c < 16; c++) acc += wr[c] * st[c * 24 + p];
        sg[i] = acc;
    }
    __syncthreads();

    for (int i = tid; i < MIP * 24; i += 512) {
        int c = i / 24, p = i % 24;
        int g = c >> 4;
        float acc = 0.f;
        #pragma unroll
        for (int kh = 0; kh < 7; kh++)
            acc += sg[(g * 7 + kh) * 24 + p] * sy[c * 32 + p + kh];
        sz[c * 24 + p] = acc;
    }
    cp_wait0();
    __syncthreads();

    {
        const int og = tid >> 1;
        const int q  = tid & 1;
        unsigned long long acc[6];
        #pragma unroll
        for (int k = 0; k < 6; k++) acc[k] = 0ull;
        #pragma unroll 4
        for (int c = 0; c < MIP; c++) {
            float wv = sw[og * 65 + c];
            unsigned long long wp = pack2(wv, wv);
            const longlong2* zp = (const longlong2*)&sz[c * 24 + q * 12];
            longlong2 za = zp[0];
            longlong2 zb = zp[1];
            longlong2 zc = zp[2];
            acc[0] = ffma2(wp, (unsigned long long)za.x, acc[0]);
            acc[1] = ffma2(wp, (unsigned long long)za.y, acc[1]);
            acc[2] = ffma2(wp, (unsigned long long)zb.x, acc[2]);
            acc[3] = ffma2(wp, (unsigned long long)zb.y, acc[3]);
            acc[4] = ffma2(wp, (unsigned long long)zc.x, acc[4]);
            acc[5] = ffma2(wp, (unsigned long long)zc.y, acc[5]);
        }
        float bo = sbc[og];
        float* op = outbuf + ((size_t)b * CIN + og) * 96 + p0 + q * 12;
        #pragma unroll
        for (int k = 0; k < 6; k++) {
            float lo, hi;
            unpack2(acc[k], lo, hi);
            op[2 * k]     = 1.f / (1.f + __expf(-(lo + bo)));
            op[2 * k + 1] = 1.f / (1.f + __expf(-(hi + bo)));
        }
    }
}

// ===================== K4: out = x * a_h * a_w, 2 float4 per thread =====================
// grid = (6, NB*CIN), block = 192; pair index t2 in [0,1152), elems 2*t2, 2*t2+1
__global__ void k_final(const float4* __restrict__ x, float4* __restrict__ out) {
    int t2 = blockIdx.x * 192 + threadIdx.x;
    int bc = blockIdx.y;
    int row = t2 / 12;
    int jf  = (t2 % 12) * 2;

    float h = __ldg(g_ah + (size_t)bc * 96 + row);
    const float4* aw4 = (const float4*)g_aw;
    float4 w0 = __ldg(aw4 + (size_t)bc * 24 + jf);
    float4 w1 = __ldg(aw4 + (size_t)bc * 24 + jf + 1);

    size_t idx = (size_t)bc * 2304 + 2 * t2;
    float4 x0 = __ldg(x + idx);
    float4 x1 = __ldg(x + idx + 1);

    float4 r0, r1;
    r0.x = x0.x * h * w0.x; r0.y = x0.y * h * w0.y;
    r0.z = x0.z * h * w0.z; r0.w = x0.w * h * w0.w;
    r1.x = x1.x * h * w1.x; r1.y = x1.y * h * w1.y;
    r1.z = x1.z * h * w1.z; r1.w = x1.w * h * w1.w;
    out[idx]     = r0;
    out[idx + 1] = r1;
}

// ===================== launch =====================
extern "C" void kernel_launch(void* const* d_in, const int* in_sizes, int n_in,
                              void* d_out, int out_size) {
    const float* x     = (const float*)d_in[0];
    const float* w_c1  = (const float*)d_in[1];
    const float* b_c1  = (const float*)d_in[2];
    const float* i1w1  = (const float*)d_in[3];
    const float* i1b1  = (const float*)d_in[4];
    const float* i1w2  = (const float*)d_in[5];
    const float* i1b2  = (const float*)d_in[6];
    const float* bng   = (const float*)d_in[7];
    const float* bnb   = (const float*)d_in[8];
    const float* bnm   = (const float*)d_in[9];
    const float* bnv   = (const float*)d_in[10];
    const float* ihw1  = (const float*)d_in[11];
    const float* ihb1  = (const float*)d_in[12];
    const float* ihw2  = (const float*)d_in[13];
    const float* ihb2  = (const float*)d_in[14];
    const float* w_h   = (const float*)d_in[15];
    const float* b_h   = (const float*)d_in[16];
    const float* iww1  = (const float*)d_in[17];
    const float* iwb1  = (const float*)d_in[18];
    const float* iww2  = (const float*)d_in[19];
    const float* iwb2  = (const float*)d_in[20];
    const float* w_w   = (const float*)d_in[21];
    const float* b_w   = (const float*)d_in[22];

    cudaFuncSetAttribute(k_cinv1, cudaFuncAttributeMaxDynamicSharedMemorySize,
                         C1_SMEM_FLOATS * 4);
    cudaFuncSetAttribute(k_inv2, cudaFuncAttributeMaxDynamicSharedMemorySize,
                         C2_SMEM_FLOATS * 4);

    k_means<<<NB * CIN, 256>>>(x);
    k_cinv1<<<NB * 8, 512, C1_SMEM_FLOATS * 4>>>(w_c1, b_c1, i1w1, i1b1, i1w2, i1b2,
                                                 bng, bnb, bnm, bnv);
    k_inv2<<<NB * 2 * 4, 512, C2_SMEM_FLOATS * 4>>>(ihw1, ihb1, ihw2, ihb2, w_h, b_h,
                                                    iww1, iwb1, iww2, iwb2, w_w, b_w);
    k_final<<<dim3(6, NB * CIN), 192>>>((const float4*)x, (float4*)d_out);
}

// round 5
// speedup vs baseline: 2.3969x; 1.0617x over previous
#include <cuda_runtime.h>
#include <math.h>

#define NB   16
#define CIN  256
#define MIP  64
#define SEQ  192

// ---- scratch (device globals; no allocation allowed) ----
__device__ float g_y0[NB * CIN * SEQ];    // pooled + concat (b, 256, 192)
__device__ float g_y2[NB * MIP * SEQ];    // after involution1 + BN + hswish
__device__ float g_ah[NB * CIN * 96];     // sigmoid attention (h)
__device__ float g_aw[NB * CIN * 96];     // sigmoid attention (w)

// ---------------- helpers ----------------
__device__ __forceinline__ void cp_async4(void* smem_dst, const void* gmem_src) {
    unsigned s = (unsigned)__cvta_generic_to_shared(smem_dst);
    asm volatile("cp.async.ca.shared.global [%0], [%1], 4;" :: "r"(s), "l"(gmem_src));
}
__device__ __forceinline__ void cp_commit() {
    asm volatile("cp.async.commit_group;");
}
__device__ __forceinline__ void cp_wait0() {
    asm volatile("cp.async.wait_group 0;" ::: "memory");
}
__device__ __forceinline__ void cp_wait1() {
    asm volatile("cp.async.wait_group 1;" ::: "memory");
}
__device__ __forceinline__ unsigned long long pack2(float a, float b) {
    unsigned long long r;
    asm("mov.b64 %0, {%1, %2};" : "=l"(r) : "f"(a), "f"(b));
    return r;
}
__device__ __forceinline__ unsigned long long ffma2(unsigned long long a,
                                                    unsigned long long b,
                                                    unsigned long long c) {
    unsigned long long d;
    asm("fma.rn.f32x2 %0, %1, %2, %3;" : "=l"(d) : "l"(a), "l"(b), "l"(c));
    return d;
}
__device__ __forceinline__ void unpack2(unsigned long long v, float& lo, float& hi) {
    asm("mov.b64 {%0, %1}, %2;" : "=f"(lo), "=f"(hi) : "l"(v));
}

// ===================== K1: row & col means per (b,c) plane =====================
// grid = NB*CIN, block = 256. Stage plane in smem (9 coalesced float4 LDGs per
// thread, MLP=9), then 96 row-sum threads + 96 col-sum threads.
__global__ void k_means(const float* __restrict__ x) {
    __shared__ float4 sp4[96 * 25];     // row stride 25 float4 (pad)
    const int bc  = blockIdx.x;
    const int tid = threadIdx.x;
    const float4* xp = (const float4*)(x + (size_t)bc * 9216);

    float4 v[9];
    #pragma unroll
    for (int k = 0; k < 9; k++) v[k] = __ldg(&xp[tid + k * 256]);
    #pragma unroll
    for (int k = 0; k < 9; k++) {
        int i = tid + k * 256;
        int r = i / 24, c4 = i % 24;
        sp4[r * 25 + c4] = v[k];
    }
    __syncthreads();

    if (tid < 96) {
        const float4* rp = &sp4[tid * 25];
        float4 a = make_float4(0.f, 0.f, 0.f, 0.f);
        #pragma unroll 6
        for (int j = 0; j < 24; j++) {
            float4 q = rp[j];
            a.x += q.x; a.y += q.y; a.z += q.z; a.w += q.w;
        }
        float s = (a.x + a.y) + (a.z + a.w);
        g_y0[(size_t)bc * SEQ + tid] = s * (1.f / 96.f);
    } else if (tid < 192) {
        int c = tid - 96;
        const float* spf = (const float*)sp4;    // row stride 100 floats
        float s0 = 0.f, s1 = 0.f, s2 = 0.f, s3 = 0.f;
        #pragma unroll 8
        for (int r = 0; r < 96; r += 4) {
            s0 += spf[(r + 0) * 100 + c];
            s1 += spf[(r + 1) * 100 + c];
            s2 += spf[(r + 2) * 100 + c];
            s3 += spf[(r + 3) * 100 + c];
        }
        g_y0[(size_t)bc * SEQ + 96 + c] = ((s0 + s1) + (s2 + s3)) * (1.f / 96.f);
    }
}

// ========== K2: fused conv1x1(256->64) + involution(192) + BN + hswish ==========
#define C1_SMEM_FLOATS 32756
__global__ void __launch_bounds__(512, 1)
k_cinv1(const float* __restrict__ wc1, const float* __restrict__ bc1,
        const float* __restrict__ w1, const float* __restrict__ b1,
        const float* __restrict__ w2, const float* __restrict__ b2,
        const float* __restrict__ bng, const float* __restrict__ bnb,
        const float* __restrict__ bnm, const float* __restrict__ bnv) {
    extern __shared__ float dyn[];
    float* sw1  = dyn;                 // 16448 (64 x pad257)
    float* sww1 = sw1  + 16448;        // 1024
    float* sb1  = sww1 + 1024;         // 16
    float* sw2  = sb1  + 16;           // 3136
    float* sb2  = sw2  + 3136;         // 196
    float* sbc1 = sb2  + 196;          // 64
    float* sbn  = sbc1 + 64;           // 256
    float* ys   = sbn  + 256;          // 8192 (256 x 32)
    float* y1s  = ys   + 8192;         // 2368 (64 x pad37)
    float* st   = y1s  + 2368;         // 384
    float* sg   = st   + 384;          // 672

    const int b   = blockIdx.x >> 3;
    const int p0  = (blockIdx.x & 7) * 24;
    const int tid = threadIdx.x;

    for (int i = tid; i < 64 * 256; i += 512)
        cp_async4(&sw1[(i >> 8) * 257 + (i & 255)], wc1 + i);
    for (int i = tid; i < 1024; i += 512) cp_async4(&sww1[i], w1 + i);
    if (tid < 16)  cp_async4(&sb1[tid], b1 + tid);
    for (int i = tid; i < 3136; i += 512) cp_async4(&sw2[i], w2 + i);
    if (tid < 196) cp_async4(&sb2[tid], b2 + tid);
    if (tid < 64)  cp_async4(&sbc1[tid], bc1 + tid);
    if (tid < 64)        cp_async4(&sbn[tid], bng + tid);
    else if (tid < 128)  cp_async4(&sbn[tid], bnb + tid - 64);
    else if (tid < 192)  cp_async4(&sbn[tid], bnm + tid - 128);
    else if (tid < 256)  cp_async4(&sbn[tid], bnv + tid - 192);
    cp_commit();

    for (int i = tid; i < CIN * 32; i += 512) {
        int c = i >> 5, ps = i & 31;
        int gp = p0 - 3 + ps;
        ys[i] = (gp >= 0 && gp < SEQ) ? g_y0[((size_t)b * CIN + c) * SEQ + gp] : 0.f;
    }
    cp_wait0();
    __syncthreads();

    // conv1x1 (packed f32x2): y1[o][ps], 64 o x 32 ps
    {
        const int o  = tid & 63;
        const int pg = tid >> 6;
        unsigned long long a0 = 0ull, a1 = 0ull;
        #pragma unroll 8
        for (int c = 0; c < CIN; c++) {
            float wv = sw1[o * 257 + c];
            unsigned long long wp = pack2(wv, wv);
            longlong2 y = *(const longlong2*)&ys[c * 32 + pg * 4];
            a0 = ffma2(wp, (unsigned long long)y.x, a0);
            a1 = ffma2(wp, (unsigned long long)y.y, a1);
        }
        float v0, v1, v2, v3;
        unpack2(a0, v0, v1); unpack2(a1, v2, v3);
        float bo = sbc1[o];
        float* dst = &y1s[o * 37 + pg * 4];
        int gbase = p0 - 3 + pg * 4;
        dst[0] = (gbase + 0 >= 0 && gbase + 0 < SEQ) ? v0 + bo : 0.f;
        dst[1] = (gbase + 1 >= 0 && gbase + 1 < SEQ) ? v1 + bo : 0.f;
        dst[2] = (gbase + 2 >= 0 && gbase + 2 < SEQ) ? v2 + bo : 0.f;
        dst[3] = (gbase + 3 >= 0 && gbase + 3 < SEQ) ? v3 + bo : 0.f;
    }
    __syncthreads();

    if (tid < 384) {
        int r = tid / 24, p = tid % 24;
        float acc = sb1[r];
        const float* wr = &sww1[r * 64];
        #pragma unroll 8
        for (int c = 0; c < MIP; c++) acc += wr[c] * y1s[c * 37 + 3 + p];
        st[r * 24 + p] = acc;
    }
    __syncthreads();

    for (int i = tid; i < 28 * 24; i += 512) {
        int r = i / 24, p = i % 24;
        int g = r / 7, kh = r % 7;
        int row = g * 49 + kh * 7 + 3;
        float acc = sb2[row];
        const float* wr = &sw2[row * 16];
        #pragma unroll
        for (int c = 0; c < 16; c++) acc += wr[c] * st[c * 24 + p];
        sg[i] = acc;
    }
    __syncthreads();

    for (int i = tid; i < MIP * 24; i += 512) {
        int c = i / 24, p = i % 24;
        int g = c >> 4;
        float acc = 0.f;
        #pragma unroll
        for (int kh = 0; kh < 7; kh++)
            acc += sg[(g * 7 + kh) * 24 + p] * y1s[c * 37 + p + kh];
        float sc = sbn[c] * rsqrtf(sbn[192 + c] + 1e-5f);
        float v  = (acc - sbn[128 + c]) * sc + sbn[64 + c];
        float hs = v * fminf(fmaxf(v + 3.f, 0.f), 6.f) * (1.f / 6.f);
        g_y2[((size_t)b * MIP + c) * SEQ + p0 + p] = hs;
    }
}

// ========== K3: involution (96-seq, h/w half) + conv1x1 64->256 + sigmoid ==========
#define C2_SMEM_FLOATS 25908
__global__ void __launch_bounds__(512, 2)
k_inv2(const float* __restrict__ w1h, const float* __restrict__ b1h,
       const float* __restrict__ w2h, const float* __restrict__ b2h,
       const float* __restrict__ wch, const float* __restrict__ bch,
       const float* __restrict__ w1w, const float* __restrict__ b1w,
       const float* __restrict__ w2w, const float* __restrict__ b2w,
       const float* __restrict__ wcw, const float* __restrict__ bcw) {
    extern __shared__ float dyn[];
    float* sw   = dyn;               // 16640 (256 x pad65)
    float* sww1 = sw   + 16640;      // 1024
    float* sb1  = sww1 + 1024;       // 16
    float* sw2  = sb1  + 16;         // 3136
    float* sb2  = sw2  + 3136;       // 196
    float* sbc  = sb2  + 196;        // 256
    float* sy   = sbc  + 256;        // 2048
    float* st   = sy   + 2048;       // 384
    float* sg   = st   + 384;        // 672
    float* sz   = sg   + 672;        // 1536

    const int bid  = blockIdx.x;
    const int b    = bid >> 3;
    const int rest = bid & 7;
    const int half = rest >> 2;
    const int p0   = (rest & 3) * 24;
    const int tid  = threadIdx.x;

    const float* w1 = half ? w1w : w1h;
    const float* b1 = half ? b1w : b1h;
    const float* w2 = half ? w2w : w2h;
    const float* b2 = half ? b2w : b2h;
    const float* wc = half ? wcw : wch;
    const float* bc = half ? bcw : bch;
    float* outbuf   = half ? g_aw : g_ah;

    for (int i = tid; i < 1024; i += 512) cp_async4(&sww1[i], w1 + i);
    if (tid < 16)  cp_async4(&sb1[tid], b1 + tid);
    for (int i = tid; i < 3136; i += 512) cp_async4(&sw2[i], w2 + i);
    if (tid < 196) cp_async4(&sb2[tid], b2 + tid);
    if (tid < 256) cp_async4(&sbc[tid], bc + tid);
    cp_commit();
    for (int i = tid; i < CIN * MIP; i += 512)
        cp_async4(&sw[(i >> 6) * 65 + (i & 63)], wc + i);
    cp_commit();

    for (int i = tid; i < MIP * 32; i += 512) {
        int c = i >> 5, ps = i & 31;
        int gp = p0 - 3 + ps;
        sy[i] = (gp >= 0 && gp < 96)
              ? g_y2[((size_t)b * MIP + c) * SEQ + half * 96 + gp] : 0.f;
    }
    cp_wait1();
    __syncthreads();

    if (tid < 384) {
        int r = tid / 24, p = tid % 24;
        float acc = sb1[r];
        const float* wr = &sww1[r * 64];
        #pragma unroll 8
        for (int c = 0; c < MIP; c++) acc += wr[c] * sy[c * 32 + 3 + p];
        st[r * 24 + p] = acc;
    }
    __syncthreads();

    for (int i = tid; i < 28 * 24; i += 512) {
        int r = i / 24, p = i % 24;
        int g = r / 7, kh = r % 7;
        int row = half ? (g * 49 + 21 + kh) : (g * 49 + kh * 7 + 3);
        float acc = sb2[row];
        const float* wr = &sw2[row * 16];
        #pragma unroll
        for (int c = 0; c < 16; c++) acc += wr[c] * st[c * 24 + p];
        sg[i] = acc;
    }
    __syncthreads();

    for (int i = tid; i < MIP * 24; i += 512) {
        int c = i / 24, p = i % 24;
        int g = c >> 4;
        float acc = 0.f;
        #pragma unroll
        for (int kh = 0; kh < 7; kh++)
            acc += sg[(g * 7 + kh) * 24 + p] * sy[c * 32 + p + kh];
        sz[c * 24 + p] = acc;
    }
    cp_wait0();
    __syncthreads();

    {
        const int og = tid >> 1;
        const int q  = tid & 1;
        unsigned long long acc[6];
        #pragma unroll
        for (int k = 0; k < 6; k++) acc[k] = 0ull;
        #pragma unroll 4
        for (int c = 0; c < MIP; c++) {
            float wv = sw[og * 65 + c];
            unsigned long long wp = pack2(wv, wv);
            const longlong2* zp = (const longlong2*)&sz[c * 24 + q * 12];
            longlong2 za = zp[0];
            longlong2 zb = zp[1];
            longlong2 zc = zp[2];
            acc[0] = ffma2(wp, (unsigned long long)za.x, acc[0]);
            acc[1] = ffma2(wp, (unsigned long long)za.y, acc[1]);
            acc[2] = ffma2(wp, (unsigned long long)zb.x, acc[2]);
            acc[3] = ffma2(wp, (unsigned long long)zb.y, acc[3]);
            acc[4] = ffma2(wp, (unsigned long long)zc.x, acc[4]);
            acc[5] = ffma2(wp, (unsigned long long)zc.y, acc[5]);
        }
        float bo = sbc[og];
        float* op = outbuf + ((size_t)b * CIN + og) * 96 + p0 + q * 12;
        #pragma unroll
        for (int k = 0; k < 6; k++) {
            float lo, hi;
            unpack2(acc[k], lo, hi);
            op[2 * k]     = 1.f / (1.f + __expf(-(lo + bo)));
            op[2 * k + 1] = 1.f / (1.f + __expf(-(hi + bo)));
        }
    }
}

// ===================== K4: out = x * a_h * a_w, 2 float4 per thread =====================
// REVERSED traversal: earliest blocks read the tail of x (L2-resident from
// k_means' forward stream). Output stored with st.global.cs (evict-first) so
// the write stream does not evict x from L2.
// grid = (6, NB*CIN), block = 192
__global__ void k_final(const float4* __restrict__ x, float4* __restrict__ out) {
    int bc    = 4095 - (int)blockIdx.y;          // reverse plane order
    int chunk = 5 - (int)blockIdx.x;             // reverse chunk order
    int t2 = chunk * 192 + threadIdx.x;
    int row = t2 / 12;
    int jf  = (t2 % 12) * 2;

    float h = __ldg(g_ah + (size_t)bc * 96 + row);
    const float4* aw4 = (const float4*)g_aw;
    float4 w0 = __ldg(aw4 + (size_t)bc * 24 + jf);
    float4 w1 = __ldg(aw4 + (size_t)bc * 24 + jf + 1);

    size_t idx = (size_t)bc * 2304 + 2 * t2;
    float4 x0 = __ldg(x + idx);
    float4 x1 = __ldg(x + idx + 1);

    float4 r0, r1;
    r0.x = x0.x * h * w0.x; r0.y = x0.y * h * w0.y;
    r0.z = x0.z * h * w0.z; r0.w = x0.w * h * w0.w;
    r1.x = x1.x * h * w1.x; r1.y = x1.y * h * w1.y;
    r1.z = x1.z * h * w1.z; r1.w = x1.w * h * w1.w;
    __stcs(out + idx,     r0);
    __stcs(out + idx + 1, r1);
}

// ===================== launch =====================
extern "C" void kernel_launch(void* const* d_in, const int* in_sizes, int n_in,
                              void* d_out, int out_size) {
    const float* x     = (const float*)d_in[0];
    const float* w_c1  = (const float*)d_in[1];
    const float* b_c1  = (const float*)d_in[2];
    const float* i1w1  = (const float*)d_in[3];
    const float* i1b1  = (const float*)d_in[4];
    const float* i1w2  = (const float*)d_in[5];
    const float* i1b2  = (const float*)d_in[6];
    const float* bng   = (const float*)d_in[7];
    const float* bnb   = (const float*)d_in[8];
    const float* bnm   = (const float*)d_in[9];
    const float* bnv   = (const float*)d_in[10];
    const float* ihw1  = (const float*)d_in[11];
    const float* ihb1  = (const float*)d_in[12];
    const float* ihw2  = (const float*)d_in[13];
    const float* ihb2  = (const float*)d_in[14];
    const float* w_h   = (const float*)d_in[15];
    const float* b_h   = (const float*)d_in[16];
    const float* iww1  = (const float*)d_in[17];
    const float* iwb1  = (const float*)d_in[18];
    const float* iww2  = (const float*)d_in[19];
    const float* iwb2  = (const float*)d_in[20];
    const float* w_w   = (const float*)d_in[21];
    const float* b_w   = (const float*)d_in[22];

    cudaFuncSetAttribute(k_cinv1, cudaFuncAttributeMaxDynamicSharedMemorySize,
                         C1_SMEM_FLOATS * 4);
    cudaFuncSetAttribute(k_inv2, cudaFuncAttributeMaxDynamicSharedMemorySize,
                         C2_SMEM_FLOATS * 4);

    k_means<<<NB * CIN, 256>>>(x);
    k_cinv1<<<NB * 8, 512, C1_SMEM_FLOATS * 4>>>(w_c1, b_c1, i1w1, i1b1, i1w2, i1b2,
                                                 bng, bnb, bnm, bnv);
    k_inv2<<<NB * 2 * 4, 512, C2_SMEM_FLOATS * 4>>>(ihw1, ihb1, ihw2, ihb2, w_h, b_h,
                                                    iww1, iwb1, iww2, iwb2, w_w, b_w);
    k_final<<<dim3(6, NB * CIN), 192>>>((const float4*)x, (float4*)d_out);
}